// round 2
// baseline (speedup 1.0000x reference)
#include <cuda_runtime.h>
#include <stdint.h>

// Problem constants (shapes fixed by the dataset)
#define B_   32
#define C_   4
#define H_   512
#define W_   512
#define T_   64
#define NTOT (B_ * C_ * H_ * W_)          // 33,554,432 elements
#define V_   (NTOT / 4)                   // 8,388,608 float4 pairs
#define WORDS_PER_ROW 16                  // 512 bits / 32

// Scratch: per-batch row bitmaps + global double accumulator
__device__ unsigned int g_mask[B_ * H_ * WORDS_PER_ROW];  // 1 MB
__device__ double g_acc;

// ---------------------------------------------------------------------------
// Kernel 1: build mask bitmap. One block per batch (512 threads = 512 rows).
// Each thread owns one image row: iterate 64 tokens, OR 10-bit column spans
// into a register-resident 512-bit row, store 16 words. Thread (0,0) zeroes
// the accumulator (stream order makes it visible to the reduce kernel).
// ---------------------------------------------------------------------------
__global__ void mask_kernel(const float* __restrict__ pos /*[B,T,2]*/) {
    const int b = blockIdx.x;
    const int h = threadIdx.x;

    __shared__ float2 sp[T_];
    if (threadIdx.x < T_)
        sp[threadIdx.x] = reinterpret_cast<const float2*>(pos)[b * T_ + threadIdx.x];
    if (b == 0 && h == 0) g_acc = 0.0;
    __syncthreads();

    unsigned int bits[WORDS_PER_ROW];
#pragma unroll
    for (int i = 0; i < WORDS_PER_ROW; i++) bits[i] = 0u;

    for (int t = 0; t < T_; t++) {
        const float x = sp[t].x;
        const float y = sp[t].y;
        if (x > 0.0f && y > 0.0f) {
            const int yp = (int)floorf(y * (float)H_);
            if (h >= yp - 5 && h < yp + 5) {
                const int xp = (int)floorf(x * (float)W_);
                int x0 = xp - 5; if (x0 < 0) x0 = 0;
                int x1 = xp + 5; if (x1 > W_) x1 = W_;
                if (x0 < x1) {
                    const int w0 = x0 >> 5;
                    const int w1 = (x1 - 1) >> 5;
                    if (w0 == w1) {
                        const int len = x1 - x0;                     // 1..10 < 32
                        bits[w0] |= ((1u << len) - 1u) << (x0 & 31);
                    } else {
                        bits[w0] |= 0xFFFFFFFFu << (x0 & 31);
                        bits[w1] |= (1u << (x1 & 31)) - 1u;          // x1&31 in 1..9 here
                    }
                }
            }
        }
    }

    unsigned int* dst = &g_mask[(b * H_ + h) * WORDS_PER_ROW];
#pragma unroll
    for (int i = 0; i < WORDS_PER_ROW; i++) dst[i] = bits[i];
}

// ---------------------------------------------------------------------------
// Kernel 2: HBM-bound weighted SSE reduction.
// Grid fixed at 4096 x 256 => 2^20 threads; stride 2^20; exactly 8 iterations
// cover V_ = 2^23 float4s (static unroll -> front-batched LDG.128, high MLP).
// ---------------------------------------------------------------------------
#define RED_BLOCKS  4096
#define RED_THREADS 256
#define RED_STRIDE  (RED_BLOCKS * RED_THREADS)   // 1<<20
#define RED_ITERS   (V_ / RED_STRIDE)            // 8

__global__ __launch_bounds__(RED_THREADS)
void reduce_kernel(const float* __restrict__ pred, const float* __restrict__ targ) {
    const int tid = blockIdx.x * RED_THREADS + threadIdx.x;
    const float4* __restrict__ p4 = reinterpret_cast<const float4*>(pred);
    const float4* __restrict__ t4 = reinterpret_cast<const float4*>(targ);

    float acc = 0.0f;
#pragma unroll
    for (int i = 0; i < RED_ITERS; i++) {
        const int v = tid + i * RED_STRIDE;      // always < V_
        const float4 p = p4[v];
        const float4 t = t4[v];

        // decode (b, h, w-group) from float4 index
        const int w4  = v & 127;                 // group-of-4 within row
        const int row = v >> 7;                  // global (b,c,h) row
        const int h   = row & (H_ - 1);
        const int b   = row >> 11;               // /(C_*H_)
        const unsigned word = g_mask[((b << 9) + h) * WORDS_PER_ROW + (w4 >> 3)];
        const unsigned nib  = (word >> ((w4 & 7) * 4)) & 0xFu;

        const float d0 = p.x - t.x;
        const float d1 = p.y - t.y;
        const float d2 = p.z - t.z;
        const float d3 = p.w - t.w;
        acc = fmaf(d0 * d0, (nib & 1u) ? 4.0f : 1.0f, acc);
        acc = fmaf(d1 * d1, (nib & 2u) ? 4.0f : 1.0f, acc);
        acc = fmaf(d2 * d2, (nib & 4u) ? 4.0f : 1.0f, acc);
        acc = fmaf(d3 * d3, (nib & 8u) ? 4.0f : 1.0f, acc);
    }

    // warp reduce
#pragma unroll
    for (int off = 16; off > 0; off >>= 1)
        acc += __shfl_xor_sync(0xFFFFFFFFu, acc, off);

    __shared__ float warp_sums[RED_THREADS / 32];
    const int lane = threadIdx.x & 31;
    const int wid  = threadIdx.x >> 5;
    if (lane == 0) warp_sums[wid] = acc;
    __syncthreads();

    if (wid == 0) {
        float s = (lane < RED_THREADS / 32) ? warp_sums[lane] : 0.0f;
#pragma unroll
        for (int off = 4; off > 0; off >>= 1)
            s += __shfl_xor_sync(0xFFFFFFFFu, s, off);
        if (lane == 0)
            atomicAdd(&g_acc, (double)s);
    }
}

// ---------------------------------------------------------------------------
// Kernel 3: finalize — loss = mean of weighted diff^2 (WEIGHT=1.0 collapses
// base_loss + 1.0*(text_loss - base_loss) to text_loss).
// ---------------------------------------------------------------------------
__global__ void finalize_kernel(float* __restrict__ out) {
    out[0] = (float)(g_acc * (1.0 / (double)NTOT));
}

extern "C" void kernel_launch(void* const* d_in, const int* in_sizes, int n_in,
                              void* d_out, int out_size) {
    const float* pred = (const float*)d_in[0];   // predicted_noise [B,C,H,W] f32
    const float* targ = (const float*)d_in[1];   // target_noise    [B,C,H,W] f32
    // d_in[2] = text_tokens (int64) — unused by the math
    const float* pos  = (const float*)d_in[3];   // text_positions [B,T,2] f32
    float* out = (float*)d_out;

    mask_kernel<<<B_, H_>>>(pos);
    reduce_kernel<<<RED_BLOCKS, RED_THREADS>>>(pred, targ);
    finalize_kernel<<<1, 1>>>(out);
}

// round 3
// speedup vs baseline: 1.1572x; 1.1572x over previous
#include <cuda_runtime.h>
#include <stdint.h>

// Shapes fixed by the dataset
#define B_   32
#define C_   4
#define H_   512
#define W_   512
#define T_   64
#define NTOT (B_ * C_ * H_ * W_)          // 33,554,432 elements
#define V_   (NTOT / 4)                   // 8,388,608 float4 pairs

#define RED_BLOCKS  4096
#define RED_THREADS 256
// Each block: contiguous slab of 2048 float4 = 16 consecutive rows of one batch.

__device__ double g_acc;          // zero-init; re-zeroed by last block each run
__device__ unsigned int g_count;  // zero-init; re-zeroed by last block each run

__global__ __launch_bounds__(RED_THREADS)
void fused_loss_kernel(const float* __restrict__ pred,
                       const float* __restrict__ targ,
                       const float* __restrict__ pos,   // [B,T,2]
                       float* __restrict__ out) {
    const int bi  = blockIdx.x;
    const int tid = threadIdx.x;
    const int base     = bi << 11;        // first float4 index of this block's slab
    const int row_base = bi << 4;         // first global (b,c,h) row
    const int b        = row_base >> 11;  // C_*H_ = 2048 rows per batch; 16-aligned => uniform
    const int h_base   = row_base & (H_ - 1);  // 16-aligned => no wrap within block

    __shared__ unsigned int smask[16][16];   // 16 rows x 512 bits
    __shared__ float2 spos[T_];

    // ---- prologue: init shared, load this batch's token positions ----
    smask[tid >> 4][tid & 15] = 0u;
    if (tid < T_)
        spos[tid] = reinterpret_cast<const float2*>(pos)[b * T_ + tid];
    __syncthreads();

    // ---- build 16-row mask: thread handles row (tid&15), 4 tokens ----
    {
        const int lr = tid & 15;
        const int h  = h_base + lr;
        const int t0 = (tid >> 4) << 2;
#pragma unroll
        for (int k = 0; k < 4; k++) {
            const float x = spos[t0 + k].x;
            const float y = spos[t0 + k].y;
            if (x > 0.0f && y > 0.0f) {
                const int yp = (int)floorf(y * (float)H_);
                if (h >= yp - 5 && h < yp + 5) {
                    const int xp = (int)floorf(x * (float)W_);
                    int x0 = xp - 5; if (x0 < 0) x0 = 0;
                    int x1 = xp + 5; if (x1 > W_) x1 = W_;
                    if (x0 < x1) {
                        const int w0 = x0 >> 5;
                        const int w1 = (x1 - 1) >> 5;
                        if (w0 == w1) {
                            atomicOr(&smask[lr][w0],
                                     ((1u << (x1 - x0)) - 1u) << (x0 & 31));
                        } else {
                            atomicOr(&smask[lr][w0], 0xFFFFFFFFu << (x0 & 31));
                            atomicOr(&smask[lr][w1], (1u << (x1 & 31)) - 1u);
                        }
                    }
                }
            }
        }
    }
    __syncthreads();

    // ---- preload the 8 weight-nibbles this thread needs ----
    // v = base + tid + i*256  =>  local row = i*2 + (tid>>7); w4 = tid & 127.
    const int widx  = (tid & 127) >> 3;
    const int shift = (tid & 7) << 2;
    const int hi    = tid >> 7;            // 0 or 1
    unsigned int nib[8];
#pragma unroll
    for (int i = 0; i < 8; i++)
        nib[i] = (smask[(i << 1) + hi][widx] >> shift) & 0xFu;

    // ---- HBM-bound hot loop: 16 coalesced LDG.128, pure FFMA ----
    const float4* __restrict__ p4 = reinterpret_cast<const float4*>(pred);
    const float4* __restrict__ t4 = reinterpret_cast<const float4*>(targ);

    float acc = 0.0f;
#pragma unroll
    for (int i = 0; i < 8; i++) {
        const int v = base + tid + (i << 8);
        const float4 p = p4[v];
        const float4 t = t4[v];
        const float d0 = p.x - t.x;
        const float d1 = p.y - t.y;
        const float d2 = p.z - t.z;
        const float d3 = p.w - t.w;
        const unsigned int m = nib[i];
        acc = fmaf(d0 * d0, (m & 1u) ? 4.0f : 1.0f, acc);
        acc = fmaf(d1 * d1, (m & 2u) ? 4.0f : 1.0f, acc);
        acc = fmaf(d2 * d2, (m & 4u) ? 4.0f : 1.0f, acc);
        acc = fmaf(d3 * d3, (m & 8u) ? 4.0f : 1.0f, acc);
    }

    // ---- block reduction ----
#pragma unroll
    for (int off = 16; off > 0; off >>= 1)
        acc += __shfl_xor_sync(0xFFFFFFFFu, acc, off);

    __shared__ float warp_sums[RED_THREADS / 32];
    const int lane = tid & 31;
    const int wid  = tid >> 5;
    if (lane == 0) warp_sums[wid] = acc;
    __syncthreads();

    if (tid == 0) {
        float s = 0.0f;
#pragma unroll
        for (int wj = 0; wj < RED_THREADS / 32; wj++) s += warp_sums[wj];
        atomicAdd(&g_acc, (double)s);

        // last-block-done: finalize inline, then reset state for next replay
        __threadfence();
        const unsigned int ticket = atomicAdd(&g_count, 1u);
        if (ticket == RED_BLOCKS - 1) {
            __threadfence();
            const double total = g_acc;
            out[0] = (float)(total * (1.0 / (double)NTOT));
            g_acc   = 0.0;   // restore invariant for the next graph replay
            g_count = 0u;
        }
    }
}

extern "C" void kernel_launch(void* const* d_in, const int* in_sizes, int n_in,
                              void* d_out, int out_size) {
    const float* pred = (const float*)d_in[0];   // predicted_noise [B,C,H,W] f32
    const float* targ = (const float*)d_in[1];   // target_noise    [B,C,H,W] f32
    // d_in[2] = text_tokens (int64) — mathematically unused
    const float* pos  = (const float*)d_in[3];   // text_positions [B,T,2] f32
    float* out = (float*)d_out;

    fused_loss_kernel<<<RED_BLOCKS, RED_THREADS>>>(pred, targ, pos, out);
}